// round 1
// baseline (speedup 1.0000x reference)
#include <cuda_runtime.h>
#include <math.h>

#define S_LEN 32
#define T_LEN 32
#define BB    64
#define H     512
#define H4    2048

// Persistent grid state (device globals: allocation-free).
__device__ float g_Sx[S_LEN][BB][H];   // s_step
__device__ float g_Sh[S_LEN][BB][H];   // s_h
__device__ float g_Sm[S_LEN][BB][H];   // s_m (cell state)
__device__ float g_Tx[T_LEN][BB][H];   // t_step
__device__ float g_Th[T_LEN][BB][H];   // t_h
__device__ float g_Tm[T_LEN][BB][H];   // t_m
__device__ float g_hmid[S_LEN][BB][H];
__device__ float g_ZS[S_LEN][BB][H4];  // s_x @ Wk
__device__ float g_ZT[S_LEN][BB][H4];  // t_x @ Wk

__device__ __forceinline__ float sigf(float x) { return 1.0f / (1.0f + expf(-x)); }

__global__ void init_kernel(const float* __restrict__ src, const float* __restrict__ tgt) {
    int idx = blockIdx.x * blockDim.x + threadIdx.x;
    const int n = S_LEN * BB * H;
    if (idx < n) {
        ((float*)g_Sx)[idx] = src[idx];
        ((float*)g_Tx)[idx] = tgt[idx];
        ((float*)g_Sh)[idx] = 0.0f;
        ((float*)g_Sm)[idx] = 0.0f;
        ((float*)g_Th)[idx] = 0.0f;
        ((float*)g_Tm)[idx] = 0.0f;
    }
}

// ---------------------------------------------------------------------------
// Phase A (per wave d): for every active cell (i, j=d-i) compute
//   hmid[i]  = [Sh[i] | Th[j]] @ W_H2h + b_H2h      (K=1024, N=512)
//   ZS[i]    = Sx[i] @ Wk                           (K=512,  N=2048)
//   ZT[i]    = Tx[j] @ Wk                           (K=512,  N=2048)
// Tiling: 64x128 output tile per block, 256 threads, 4x8 per-thread microtile.
// grid = (4 + 16 + 16 = 36, ncells)
// ---------------------------------------------------------------------------
__global__ __launch_bounds__(256) void phaseA(int d,
                                              const float* __restrict__ W_H2h,
                                              const float* __restrict__ b_H2h,
                                              const float* __restrict__ Wk) {
    const int i0 = (d - 31 > 0) ? d - 31 : 0;
    const int i  = i0 + blockIdx.y;
    const int j  = d - i;
    const int t  = blockIdx.x;

    const float* A0;
    const float* A1 = nullptr;             // second half of concat (hmid only)
    const float* Bm;
    const float* bias = nullptr;
    float* Out;
    int K, ldb, ldo, n0;

    if (t < 4) {                 // hmid
        n0 = t * 128; K = 2 * H; ldb = H; ldo = H;
        Bm = W_H2h; Out = &g_hmid[i][0][0]; bias = b_H2h;
        A0 = &g_Sh[i][0][0]; A1 = &g_Th[j][0][0];
    } else if (t < 20) {         // ZS
        n0 = (t - 4) * 128; K = H; ldb = H4; ldo = H4;
        Bm = Wk; Out = &g_ZS[i][0][0]; A0 = &g_Sx[i][0][0];
    } else {                     // ZT
        n0 = (t - 20) * 128; K = H; ldb = H4; ldo = H4;
        Bm = Wk; Out = &g_ZT[i][0][0]; A0 = &g_Tx[j][0][0];
    }

    __shared__ float As[64][37];     // A tile (row-major, padded: conflict-free)
    __shared__ float Bs[32][128];    // B tile

    const int tid = threadIdx.x;
    const int tx = tid & 15;         // 16 col groups
    const int ty = tid >> 4;         // 16 row groups

    float acc[4][8];
#pragma unroll
    for (int r = 0; r < 4; r++)
#pragma unroll
        for (int c = 0; c < 8; c++) acc[r][c] = 0.0f;

    for (int k0 = 0; k0 < K; k0 += 32) {
        // ---- load A tile (64 x 32), coalesced float4 ----
        const float* Ab = A0;
        int kk0 = k0;
        if (A1 != nullptr && k0 >= H) { Ab = A1; kk0 = k0 - H; }
#pragma unroll
        for (int it = 0; it < 2; it++) {
            int fidx = tid + it * 256;          // 0..511
            int row = fidx >> 3;
            int c4  = (fidx & 7) * 4;
            float4 v = *(const float4*)(Ab + row * H + kk0 + c4);
            As[row][c4 + 0] = v.x; As[row][c4 + 1] = v.y;
            As[row][c4 + 2] = v.z; As[row][c4 + 3] = v.w;
        }
        // ---- load B tile (32 x 128), coalesced float4 ----
#pragma unroll
        for (int it = 0; it < 4; it++) {
            int fidx = tid + it * 256;          // 0..1023
            int row = fidx >> 5;
            int c4  = (fidx & 31) * 4;
            *(float4*)(&Bs[row][c4]) = *(const float4*)(Bm + (k0 + row) * ldb + n0 + c4);
        }
        __syncthreads();

#pragma unroll 8
        for (int kk = 0; kk < 32; kk++) {
            float a[4];
#pragma unroll
            for (int r = 0; r < 4; r++) a[r] = As[ty * 4 + r][kk];
            float4 b0 = *(float4*)(&Bs[kk][tx * 4]);
            float4 b1 = *(float4*)(&Bs[kk][64 + tx * 4]);
            float bb[8] = {b0.x, b0.y, b0.z, b0.w, b1.x, b1.y, b1.z, b1.w};
#pragma unroll
            for (int r = 0; r < 4; r++)
#pragma unroll
                for (int c = 0; c < 8; c++) acc[r][c] += a[r] * bb[c];
        }
        __syncthreads();
    }

    // ---- write output tile ----
#pragma unroll
    for (int r = 0; r < 4; r++) {
        int m = ty * 4 + r;
#pragma unroll
        for (int half = 0; half < 2; half++) {
            int n = n0 + half * 64 + tx * 4;
            float4 v;
            v.x = acc[r][half * 4 + 0];
            v.y = acc[r][half * 4 + 1];
            v.z = acc[r][half * 4 + 2];
            v.w = acc[r][half * 4 + 3];
            if (bias != nullptr) {
                v.x += bias[n + 0]; v.y += bias[n + 1];
                v.z += bias[n + 2]; v.w += bias[n + 3];
            }
            *(float4*)(Out + m * ldo + n) = v;
        }
    }
}

// ---------------------------------------------------------------------------
// Phase B (per wave d): for every active cell (i, j=d-i) compute
//   R = hmid[i] @ W_rec  (K=512), gate-grouped columns {g*512+n0 .. +63},
// then fused LSTM gates for BOTH the source and target cell.
// grid = (8, ncells), block 256; per-block output: 64 rows x (4 gates x 64 cols)
// ---------------------------------------------------------------------------
__global__ __launch_bounds__(256) void phaseB(int d,
                                              const float* __restrict__ Wr,
                                              const float* __restrict__ b_lstm) {
    const int i0 = (d - 31 > 0) ? d - 31 : 0;
    const int i  = i0 + blockIdx.y;
    const int j  = d - i;
    const int n0 = blockIdx.x * 64;

    __shared__ float As[64][37];
    __shared__ float Bs[32][256];

    const float* A0 = &g_hmid[i][0][0];
    const int tid = threadIdx.x;
    const int tx = tid & 15;
    const int ty = tid >> 4;

    float acc[4][4][4];   // [gate][row][col]
#pragma unroll
    for (int g = 0; g < 4; g++)
#pragma unroll
        for (int r = 0; r < 4; r++)
#pragma unroll
            for (int c = 0; c < 4; c++) acc[g][r][c] = 0.0f;

    for (int k0 = 0; k0 < H; k0 += 32) {
        // A tile (64 x 32)
#pragma unroll
        for (int it = 0; it < 2; it++) {
            int fidx = tid + it * 256;
            int row = fidx >> 3;
            int c4  = (fidx & 7) * 4;
            float4 v = *(const float4*)(A0 + row * H + k0 + c4);
            As[row][c4 + 0] = v.x; As[row][c4 + 1] = v.y;
            As[row][c4 + 2] = v.z; As[row][c4 + 3] = v.w;
        }
        // B tile: 32 rows x 4 gate-chunks of 64 cols
#pragma unroll
        for (int it = 0; it < 8; it++) {
            int fidx = tid + it * 256;          // 0..2047
            int row = fidx >> 6;
            int c4  = (fidx & 63) * 4;          // 0..252
            int g   = c4 >> 6;
            int nl  = c4 & 63;
            *(float4*)(&Bs[row][c4]) = *(const float4*)(Wr + (k0 + row) * H4 + g * H + n0 + nl);
        }
        __syncthreads();

#pragma unroll 8
        for (int kk = 0; kk < 32; kk++) {
            float a[4];
#pragma unroll
            for (int r = 0; r < 4; r++) a[r] = As[ty * 4 + r][kk];
#pragma unroll
            for (int g = 0; g < 4; g++) {
                float4 b = *(float4*)(&Bs[kk][g * 64 + tx * 4]);
                float bb[4] = {b.x, b.y, b.z, b.w};
#pragma unroll
                for (int r = 0; r < 4; r++)
#pragma unroll
                    for (int c = 0; c < 4; c++) acc[g][r][c] += a[r] * bb[c];
            }
        }
        __syncthreads();
    }

    // ---- fused LSTM gate epilogue (source cell + target cell share R) ----
    const float* ZS = &g_ZS[i][0][0];
    const float* ZT = &g_ZT[i][0][0];
    float* Sm = &g_Sm[i][0][0];
    float* Sx = &g_Sx[i][0][0];
    float* Sh = &g_Sh[i][0][0];
    float* Tm = &g_Tm[j][0][0];
    float* Tx = &g_Tx[j][0][0];
    float* Th = &g_Th[j][0][0];

#pragma unroll
    for (int r = 0; r < 4; r++) {
        int m = ty * 4 + r;
#pragma unroll
        for (int c = 0; c < 4; c++) {
            int n = n0 + tx * 4 + c;
            float bi = b_lstm[n];
            float bf = b_lstm[H + n];
            float bg = b_lstm[2 * H + n];
            float bo = b_lstm[3 * H + n];
            float ri = acc[0][r][c], rf = acc[1][r][c];
            float rg = acc[2][r][c], ro = acc[3][r][c];

            // source LSTM cell: x = s_step, h = hmid, c = s_m
            {
                float zi = ri + ZS[m * H4 + n]         + bi;
                float zf = rf + ZS[m * H4 + H + n]     + bf;
                float zg = rg + ZS[m * H4 + 2 * H + n] + bg;
                float zo = ro + ZS[m * H4 + 3 * H + n] + bo;
                float c2 = sigf(zf) * Sm[m * H + n] + sigf(zi) * tanhf(zg);
                float h2 = sigf(zo) * tanhf(c2);
                Sm[m * H + n] = c2;
                Sx[m * H + n] = h2;
                Sh[m * H + n] = h2;
            }
            // target LSTM cell: x = t_step, h = hmid, c = t_m
            {
                float zi = ri + ZT[m * H4 + n]         + bi;
                float zf = rf + ZT[m * H4 + H + n]     + bf;
                float zg = rg + ZT[m * H4 + 2 * H + n] + bg;
                float zo = ro + ZT[m * H4 + 3 * H + n] + bo;
                float c2 = sigf(zf) * Tm[m * H + n] + sigf(zi) * tanhf(zg);
                float h2 = sigf(zo) * tanhf(c2);
                Tm[m * H + n] = c2;
                Tx[m * H + n] = h2;
                Th[m * H + n] = h2;
            }
        }
    }
}

__global__ void copy_out(float* __restrict__ out) {
    int idx = blockIdx.x * blockDim.x + threadIdx.x;
    const int n = S_LEN * BB * H;
    if (idx < n) {
        out[idx]     = ((float*)g_Sx)[idx];   // source_out [S, B, H]
        out[n + idx] = ((float*)g_Tx)[idx];   // t_final[0] [T, B, H]
    }
}

extern "C" void kernel_launch(void* const* d_in, const int* in_sizes, int n_in,
                              void* d_out, int out_size) {
    const float* source = (const float*)d_in[0];
    const float* target = (const float*)d_in[1];
    const float* W_H2h  = (const float*)d_in[2];
    const float* b_H2h  = (const float*)d_in[3];
    const float* Wk     = (const float*)d_in[4];
    const float* Wr     = (const float*)d_in[5];
    const float* b_lstm = (const float*)d_in[6];
    float* out = (float*)d_out;

    const int N = S_LEN * BB * H;
    init_kernel<<<(N + 255) / 256, 256>>>(source, target);

    for (int d = 0; d < S_LEN + T_LEN - 1; d++) {
        int lo = (d - 31 > 0) ? d - 31 : 0;
        int hi = (d < 31) ? d : 31;
        int nc = hi - lo + 1;
        phaseA<<<dim3(36, nc), 256>>>(d, W_H2h, b_H2h, Wk);
        phaseB<<<dim3(8, nc), 256>>>(d, Wr, b_lstm);
    }

    copy_out<<<(N + 255) / 256, 256>>>(out);
}

// round 3
// speedup vs baseline: 1.9376x; 1.9376x over previous
#include <cuda_runtime.h>
#include <cuda_bf16.h>
#include <stdint.h>
#include <math.h>

#define S_LEN 32
#define BB    64
#define H     512
#define H2    1024
#define H4    2048

typedef __nv_bfloat16 bf16;

// ---------------- persistent device state ----------------
__device__ bf16 g_W2h[2][H2 * H];
__device__ bf16 g_Wk [2][H * H4];
__device__ bf16 g_Wr [2][H * H4];
__device__ bf16 g_bSh[2][S_LEN][BB * H];
__device__ bf16 g_bTh[2][S_LEN][BB * H];
__device__ bf16 g_bSx[2][S_LEN][BB * H];
__device__ bf16 g_bTx[2][S_LEN][BB * H];
__device__ bf16 g_bHm[2][S_LEN][BB * H];
__device__ float g_fSm[S_LEN][BB * H];
__device__ float g_fTm[S_LEN][BB * H];
__device__ float g_fSx[S_LEN][BB * H];
__device__ float g_fTx[S_LEN][BB * H];
__device__ float g_fZS[S_LEN][BB * H4];
__device__ float g_fZT[S_LEN][BB * H4];

// ---------------- helpers ----------------
__device__ __forceinline__ float sigf(float x) { return 1.0f / (1.0f + __expf(-x)); }
__device__ __forceinline__ float tanh_fast(float x) {
    float e = __expf(2.0f * x);
    return 1.0f - 2.0f / (e + 1.0f);
}
__device__ __forceinline__ void split_store(float v, bf16* phi, bf16* plo) {
    bf16 hi = __float2bfloat16(v);
    bf16 lo = __float2bfloat16(v - __bfloat162float(hi));
    *phi = hi; *plo = lo;
}
__device__ __forceinline__ void cp16(void* smem, const void* g) {
    uint32_t s = (uint32_t)__cvta_generic_to_shared(smem);
    asm volatile("cp.async.cg.shared.global [%0], [%1], 16;\n" :: "r"(s), "l"(g));
}
__device__ __forceinline__ void cp_commit() { asm volatile("cp.async.commit_group;\n"); }
template<int N> __device__ __forceinline__ void cp_wait() {
    asm volatile("cp.async.wait_group %0;\n" :: "n"(N));
}
__device__ __forceinline__ void ldsm_x4(uint32_t& r0, uint32_t& r1, uint32_t& r2, uint32_t& r3, uint32_t addr) {
    asm volatile("ldmatrix.sync.aligned.m8n8.x4.shared.b16 {%0,%1,%2,%3},[%4];\n"
                 : "=r"(r0), "=r"(r1), "=r"(r2), "=r"(r3) : "r"(addr));
}
__device__ __forceinline__ void ldsm_x2t(uint32_t& r0, uint32_t& r1, uint32_t addr) {
    asm volatile("ldmatrix.sync.aligned.m8n8.x2.trans.shared.b16 {%0,%1},[%2];\n"
                 : "=r"(r0), "=r"(r1) : "r"(addr));
}
__device__ __forceinline__ void mma16816(float* d, const uint32_t* a, const uint32_t* b) {
    asm volatile("mma.sync.aligned.m16n8k16.row.col.f32.bf16.bf16.f32 "
                 "{%0,%1,%2,%3},{%4,%5,%6,%7},{%8,%9},{%0,%1,%2,%3};\n"
                 : "+f"(d[0]), "+f"(d[1]), "+f"(d[2]), "+f"(d[3])
                 : "r"(a[0]), "r"(a[1]), "r"(a[2]), "r"(a[3]), "r"(b[0]), "r"(b[1]));
}

#define SA 40
#define SB 136

// BM=64, BN=128, BK=32, 8 warps (2m x 4n), warp tile 32x32, m16n8k16.
// 3 split passes over K: (A,W) plane pairs (hi,hi),(hi,lo),(lo,hi).
template<int KTOT, bool CONCAT, bool GSTRIDE>
__device__ __forceinline__ void gemm_core(
    bf16* sA, bf16* sB,
    const bf16* A_hi0, const bf16* A_lo0,
    const bf16* A_hi1, const bf16* A_lo1,
    const bf16* W_hi, const bf16* W_lo, int ldw,
    int nblk, float acc[2][4][4])
{
    const int tid = threadIdx.x;
    const int lane = tid & 31;
    const int warp = tid >> 5;
    const int warp_m = warp >> 2;
    const int warp_n = warp & 3;

    const int arow = tid >> 2;
    const int acol = (tid & 3) * 8;
    const int brow0 = tid >> 4;
    const int bcol0 = (tid & 15) * 8;
    const int brow1 = brow0 + 16;
    const int gcol0 = GSTRIDE ? ((bcol0 >> 5) * H + nblk * 32 + (bcol0 & 31))
                              : (nblk * 128 + bcol0);

    const int NIT = 3 * KTOT / 32;

    auto issue = [&](int it, int st) {
        int kprime = it * 32;
        int pass = kprime / KTOT;
        int kk = kprime - pass * KTOT;
        const bf16* Aplane;
        if (CONCAT) {
            const bf16* Ah = (kk < H) ? A_hi0 : A_hi1;
            const bf16* Al = (kk < H) ? A_lo0 : A_lo1;
            int kh = kk & (H - 1);
            Aplane = ((pass == 2) ? Al : Ah) + kh;
        } else {
            Aplane = ((pass == 2) ? A_lo0 : A_hi0) + kk;
        }
        cp16(sA + st * (64 * SA) + arow * SA + acol, Aplane + arow * H + acol);
        const bf16* Wp = ((pass == 1) ? W_lo : W_hi) + (size_t)kk * ldw;
        cp16(sB + st * (32 * SB) + brow0 * SB + bcol0, Wp + brow0 * ldw + gcol0);
        cp16(sB + st * (32 * SB) + brow1 * SB + bcol0, Wp + brow1 * ldw + gcol0);
        cp_commit();
    };

    const uint32_t saBase = (uint32_t)__cvta_generic_to_shared(sA);
    const uint32_t sbBase = (uint32_t)__cvta_generic_to_shared(sB);

    issue(0, 0);
    for (int it = 0; it < NIT; ++it) {
        if (it + 1 < NIT) { issue(it + 1, (it + 1) & 1); cp_wait<1>(); }
        else              { cp_wait<0>(); }
        __syncthreads();

        const int st = it & 1;
        const uint32_t aS = saBase + st * (64 * SA) * 2;
        const uint32_t bS = sbBase + st * (32 * SB) * 2;
#pragma unroll
        for (int ks = 0; ks < 2; ks++) {
            uint32_t a[2][4];
#pragma unroll
            for (int mf = 0; mf < 2; mf++) {
                int row = warp_m * 32 + mf * 16 + (lane & 15);
                int col = ks * 16 + (lane >> 4) * 8;
                ldsm_x4(a[mf][0], a[mf][1], a[mf][2], a[mf][3],
                        aS + (uint32_t)((row * SA + col) * 2));
            }
            uint32_t b[4][2];
#pragma unroll
            for (int nf = 0; nf < 4; nf++) {
                int row = ks * 16 + (lane & 15);
                int col = nf * 32 + warp_n * 8;
                ldsm_x2t(b[nf][0], b[nf][1], bS + (uint32_t)((row * SB + col) * 2));
            }
#pragma unroll
            for (int mf = 0; mf < 2; mf++)
#pragma unroll
                for (int nf = 0; nf < 4; nf++)
                    mma16816(acc[mf][nf], a[mf], b[nf]);
        }
        __syncthreads();
    }
}

__global__ void prep_weights(const float* __restrict__ W_H2h,
                             const float* __restrict__ Wk,
                             const float* __restrict__ Wr) {
    int idx = blockIdx.x * blockDim.x + threadIdx.x;
    if (idx < H2 * H) {
        split_store(W_H2h[idx], &g_W2h[0][idx], &g_W2h[1][idx]);
    }
    if (idx < H * H4) {
        split_store(Wk[idx], &g_Wk[0][idx], &g_Wk[1][idx]);
        split_store(Wr[idx], &g_Wr[0][idx], &g_Wr[1][idx]);
    }
}

__global__ void init_state(const float* __restrict__ src, const float* __restrict__ tgt) {
    int idx = blockIdx.x * blockDim.x + threadIdx.x;
    const int n = S_LEN * BB * H;
    if (idx >= n) return;
    float s = src[idx], t = tgt[idx];
    ((float*)g_fSx)[idx] = s;
    ((float*)g_fTx)[idx] = t;
    ((float*)g_fSm)[idx] = 0.0f;
    ((float*)g_fTm)[idx] = 0.0f;
    split_store(s, &((bf16*)g_bSx[0])[idx], &((bf16*)g_bSx[1])[idx]);
    split_store(t, &((bf16*)g_bTx[0])[idx], &((bf16*)g_bTx[1])[idx]);
    bf16 z = __float2bfloat16(0.0f);
    ((bf16*)g_bSh[0])[idx] = z; ((bf16*)g_bSh[1])[idx] = z;
    ((bf16*)g_bTh[0])[idx] = z; ((bf16*)g_bTh[1])[idx] = z;
}

__global__ __launch_bounds__(256) void phaseA(int d, const float* __restrict__ b_H2h) {
    __shared__ __align__(16) bf16 sA[2 * 64 * SA];
    __shared__ __align__(16) bf16 sB[2 * 32 * SB];

    const int i0 = (d - 31 > 0) ? d - 31 : 0;
    const int i = i0 + blockIdx.y;
    const int j = d - i;
    const int t = blockIdx.x;

    const int tid = threadIdx.x;
    const int lane = tid & 31;
    const int warp = tid >> 5;
    const int warp_m = warp >> 2;
    const int warp_n = warp & 3;
    const int r0 = warp_m * 32 + (lane >> 2);
    const int c0 = warp_n * 8 + (lane & 3) * 2;

    float acc[2][4][4];
#pragma unroll
    for (int a = 0; a < 2; a++)
#pragma unroll
        for (int b = 0; b < 4; b++)
#pragma unroll
            for (int c = 0; c < 4; c++) acc[a][b][c] = 0.0f;

    if (t < 4) {
        gemm_core<H2, true, false>(sA, sB,
            g_bSh[0][i], g_bSh[1][i], g_bTh[0][j], g_bTh[1][j],
            g_W2h[0], g_W2h[1], H, t, acc);
#pragma unroll
        for (int mf = 0; mf < 2; mf++)
#pragma unroll
            for (int nf = 0; nf < 4; nf++)
#pragma unroll
                for (int rr = 0; rr < 2; rr++)
#pragma unroll
                    for (int cc = 0; cc < 2; cc++) {
                        int m = r0 + mf * 16 + rr * 8;
                        int n = t * 128 + nf * 32 + c0 + cc;
                        float v = acc[mf][nf][rr * 2 + cc] + b_H2h[n];
                        split_store(v, &g_bHm[0][i][m * H + n], &g_bHm[1][i][m * H + n]);
                    }
    } else if (t < 20) {
        int nblk = t - 4;
        gemm_core<H, false, false>(sA, sB,
            g_bSx[0][i], g_bSx[1][i], nullptr, nullptr,
            g_Wk[0], g_Wk[1], H4, nblk, acc);
#pragma unroll
        for (int mf = 0; mf < 2; mf++)
#pragma unroll
            for (int nf = 0; nf < 4; nf++)
#pragma unroll
                for (int rr = 0; rr < 2; rr++)
#pragma unroll
                    for (int cc = 0; cc < 2; cc++) {
                        int m = r0 + mf * 16 + rr * 8;
                        int n = nblk * 128 + nf * 32 + c0 + cc;
                        g_fZS[i][m * H4 + n] = acc[mf][nf][rr * 2 + cc];
                    }
    } else {
        int nblk = t - 20;
        gemm_core<H, false, false>(sA, sB,
            g_bTx[0][j], g_bTx[1][j], nullptr, nullptr,
            g_Wk[0], g_Wk[1], H4, nblk, acc);
#pragma unroll
        for (int mf = 0; mf < 2; mf++)
#pragma unroll
            for (int nf = 0; nf < 4; nf++)
#pragma unroll
                for (int rr = 0; rr < 2; rr++)
#pragma unroll
                    for (int cc = 0; cc < 2; cc++) {
                        int m = r0 + mf * 16 + rr * 8;
                        int n = nblk * 128 + nf * 32 + c0 + cc;
                        g_fZT[j][m * H4 + n] = acc[mf][nf][rr * 2 + cc];
                    }
    }
}

__global__ __launch_bounds__(256) void phaseB(int d, const float* __restrict__ b_lstm) {
    __shared__ __align__(16) bf16 sA[2 * 64 * SA];
    __shared__ __align__(16) bf16 sB[2 * 32 * SB];

    const int i0 = (d - 31 > 0) ? d - 31 : 0;
    const int i = i0 + blockIdx.y;
    const int j = d - i;
    const int nblk = blockIdx.x;

    const int tid = threadIdx.x;
    const int lane = tid & 31;
    const int warp = tid >> 5;
    const int warp_m = warp >> 2;
    const int warp_n = warp & 3;
    const int r0 = warp_m * 32 + (lane >> 2);
    const int c0 = warp_n * 8 + (lane & 3) * 2;

    float acc[2][4][4];
#pragma unroll
    for (int a = 0; a < 2; a++)
#pragma unroll
        for (int b = 0; b < 4; b++)
#pragma unroll
            for (int c = 0; c < 4; c++) acc[a][b][c] = 0.0f;

    gemm_core<H, false, true>(sA, sB,
        g_bHm[0][i], g_bHm[1][i], nullptr, nullptr,
        g_Wr[0], g_Wr[1], H4, nblk, acc);

#pragma unroll
    for (int mf = 0; mf < 2; mf++)
#pragma unroll
        for (int rr = 0; rr < 2; rr++)
#pragma unroll
            for (int cc = 0; cc < 2; cc++) {
                const int m = r0 + mf * 16 + rr * 8;
                const int nn = nblk * 32 + c0 + cc;
                const int ridx = rr * 2 + cc;
                const float ri = acc[mf][0][ridx];
                const float rf = acc[mf][1][ridx];
                const float rg = acc[mf][2][ridx];
                const float ro = acc[mf][3][ridx];
                const float bi = b_lstm[nn];
                const float bfv = b_lstm[H + nn];
                const float bg = b_lstm[2 * H + nn];
                const float bo = b_lstm[3 * H + nn];
                {
                    float zi = ri + g_fZS[i][m * H4 + nn]         + bi;
                    float zf = rf + g_fZS[i][m * H4 + H + nn]     + bfv;
                    float zg = rg + g_fZS[i][m * H4 + 2 * H + nn] + bg;
                    float zo = ro + g_fZS[i][m * H4 + 3 * H + nn] + bo;
                    float c2 = sigf(zf) * g_fSm[i][m * H + nn] + sigf(zi) * tanh_fast(zg);
                    float h2 = sigf(zo) * tanh_fast(c2);
                    g_fSm[i][m * H + nn] = c2;
                    g_fSx[i][m * H + nn] = h2;
                    bf16 hi = __float2bfloat16(h2);
                    bf16 lo = __float2bfloat16(h2 - __bfloat162float(hi));
                    g_bSx[0][i][m * H + nn] = hi; g_bSx[1][i][m * H + nn] = lo;
                    g_bSh[0][i][m * H + nn] = hi; g_bSh[1][i][m * H + nn] = lo;
                }
                {
                    float zi = ri + g_fZT[j][m * H4 + nn]         + bi;
                    float zf = rf + g_fZT[j][m * H4 + H + nn]     + bfv;
                    float zg = rg + g_fZT[j][m * H4 + 2 * H + nn] + bg;
                    float zo = ro + g_fZT[j][m * H4 + 3 * H + nn] + bo;
                    float c2 = sigf(zf) * g_fTm[j][m * H + nn] + sigf(zi) * tanh_fast(zg);
                    float h2 = sigf(zo) * tanh_fast(c2);
                    g_fTm[j][m * H + nn] = c2;
                    g_fTx[j][m * H + nn] = h2;
                    bf16 hi = __float2bfloat16(h2);
                    bf16 lo = __float2bfloat16(h2 - __bfloat162float(hi));
                    g_bTx[0][j][m * H + nn] = hi; g_bTx[1][j][m * H + nn] = lo;
                    g_bTh[0][j][m * H + nn] = hi; g_bTh[1][j][m * H + nn] = lo;
                }
            }
}

__global__ void copy_out(float* __restrict__ out) {
    int idx = blockIdx.x * blockDim.x + threadIdx.x;
    const int n = S_LEN * BB * H;
    if (idx < n) {
        out[idx]     = ((float*)g_fSx)[idx];
        out[n + idx] = ((float*)g_fTx)[idx];
    }
}

extern "C" void kernel_launch(void* const* d_in, const int* in_sizes, int n_in,
                              void* d_out, int out_size) {
    const float* source = (const float*)d_in[0];
    const float* target = (const float*)d_in[1];
    const float* W_H2h  = (const float*)d_in[2];
    const float* b_H2h  = (const float*)d_in[3];
    const float* Wk     = (const float*)d_in[4];
    const float* Wr     = (const float*)d_in[5];
    const float* b_lstm = (const float*)d_in[6];
    float* out = (float*)d_out;

    const int N = S_LEN * BB * H;
    prep_weights<<<(H * H4 + 255) / 256, 256>>>(W_H2h, Wk, Wr);
    init_state<<<(N + 255) / 256, 256>>>(source, target);

    for (int d = 0; d < 63; d++) {
        int lo = (d - 31 > 0) ? d - 31 : 0;
        int hi = (d < 31) ? d : 31;
        int nc = hi - lo + 1;
        phaseA<<<dim3(36, nc), 256>>>(d, b_H2h);
        phaseB<<<dim3(16, nc), 256>>>(d, b_lstm);
    }

    copy_out<<<(N + 255) / 256, 256>>>(out);
}

// round 4
// speedup vs baseline: 2.3115x; 1.1929x over previous
#include <cuda_runtime.h>
#include <cuda_bf16.h>
#include <stdint.h>
#include <math.h>

#define S_LEN 32
#define BB    64
#define H     512
#define H2    1024
#define H4    2048

typedef __nv_bfloat16 bf16;

// ---------------- persistent device state ----------------
__device__ bf16 g_W2h[2][H2 * H];
__device__ bf16 g_Wk [2][H * H4];
__device__ bf16 g_Wr [2][H * H4];
__device__ bf16 g_bSh[2][S_LEN][BB * H];
__device__ bf16 g_bTh[2][S_LEN][BB * H];
__device__ bf16 g_bSx[2][S_LEN][BB * H];
__device__ bf16 g_bTx[2][S_LEN][BB * H];
__device__ bf16 g_bHm[2][S_LEN][BB * H];
__device__ float g_fSm[S_LEN][BB * H];
__device__ float g_fTm[S_LEN][BB * H];
__device__ float g_fSx[S_LEN][BB * H];
__device__ float g_fTx[S_LEN][BB * H];
__device__ float g_fZS[S_LEN][BB * H4];
__device__ float g_fZT[S_LEN][BB * H4];

// ---------------- helpers ----------------
__device__ __forceinline__ float sigf(float x) { return 1.0f / (1.0f + __expf(-x)); }
__device__ __forceinline__ float tanh_fast(float x) {
    float e = __expf(2.0f * x);
    return 1.0f - 2.0f / (e + 1.0f);
}
__device__ __forceinline__ void split_store(float v, bf16* phi, bf16* plo) {
    bf16 hi = __float2bfloat16(v);
    bf16 lo = __float2bfloat16(v - __bfloat162float(hi));
    *phi = hi; *plo = lo;
}
__device__ __forceinline__ void cp16(void* smem, const void* g) {
    uint32_t s = (uint32_t)__cvta_generic_to_shared(smem);
    asm volatile("cp.async.cg.shared.global [%0], [%1], 16;\n" :: "r"(s), "l"(g));
}
__device__ __forceinline__ void cp_commit() { asm volatile("cp.async.commit_group;\n"); }
template<int N> __device__ __forceinline__ void cp_wait() {
    asm volatile("cp.async.wait_group %0;\n" :: "n"(N));
}
__device__ __forceinline__ void ldsm_x4(uint32_t& r0, uint32_t& r1, uint32_t& r2, uint32_t& r3, uint32_t addr) {
    asm volatile("ldmatrix.sync.aligned.m8n8.x4.shared.b16 {%0,%1,%2,%3},[%4];\n"
                 : "=r"(r0), "=r"(r1), "=r"(r2), "=r"(r3) : "r"(addr));
}
__device__ __forceinline__ void ldsm_x2t(uint32_t& r0, uint32_t& r1, uint32_t addr) {
    asm volatile("ldmatrix.sync.aligned.m8n8.x2.trans.shared.b16 {%0,%1},[%2];\n"
                 : "=r"(r0), "=r"(r1) : "r"(addr));
}
__device__ __forceinline__ void mma16816(float* d, const uint32_t* a, const uint32_t* b) {
    asm volatile("mma.sync.aligned.m16n8k16.row.col.f32.bf16.bf16.f32 "
                 "{%0,%1,%2,%3},{%4,%5,%6,%7},{%8,%9},{%0,%1,%2,%3};\n"
                 : "+f"(d[0]), "+f"(d[1]), "+f"(d[2]), "+f"(d[3])
                 : "r"(a[0]), "r"(a[1]), "r"(a[2]), "r"(a[3]), "r"(b[0]), "r"(b[1]));
}

// ---------------- pass-fused GEMM core ----------------
// BM=64, BN=128, BK=32, 8 warps (2m x 4n), warp tile 32x32, m16n8k16.
// Per K-tile: load A_hi, A_lo, B_hi, B_lo once; do hi*hi + hi*lo + lo*hi.
// 3-stage cp.async pipeline, ONE __syncthreads per iteration.
#define SA 40
#define SB 136
#define A_PLANE (64 * SA)                       // 2560 elems
#define B_PLANE (32 * SB)                       // 4352 elems
#define STAGE_ELEMS (2 * A_PLANE + 2 * B_PLANE) // 13824 elems
#define NSTAGE 3
#define SMEM_BYTES (NSTAGE * STAGE_ELEMS * 2)   // 82944 bytes

template<int KTOT, bool CONCAT, bool GSTRIDE>
__device__ __forceinline__ void gemm_core(
    bf16* sm,
    const bf16* A_hi0, const bf16* A_lo0,
    const bf16* A_hi1, const bf16* A_lo1,
    const bf16* W_hi, const bf16* W_lo, int ldw,
    int nblk, float acc[2][4][4])
{
    const int tid = threadIdx.x;
    const int lane = tid & 31;
    const int warp = tid >> 5;
    const int warp_m = warp >> 2;
    const int warp_n = warp & 3;

    // loader thread-constant indices
    const int arow = tid >> 2;           // 0..63
    const int acol = (tid & 3) * 8;      // 0,8,16,24
    const int brow0 = tid >> 4;          // 0..15
    const int bcol0 = (tid & 15) * 8;    // 0..120
    const int gcolB = GSTRIDE ? ((bcol0 >> 5) * H + nblk * 32 + (bcol0 & 31))
                              : (nblk * 128 + bcol0);

    const int NIT = KTOT / 32;

    auto issue = [&](int it) {
        int kk = it * 32;
        int slot = it % NSTAGE;
        bf16* st = sm + slot * STAGE_ELEMS;
        const bf16 *Ah, *Al;
        if (CONCAT && kk >= H) { Ah = A_hi1 + (kk - H); Al = A_lo1 + (kk - H); }
        else                   { Ah = A_hi0 + kk;       Al = A_lo0 + kk; }
        cp16(st + arow * SA + acol,            Ah + arow * H + acol);
        cp16(st + A_PLANE + arow * SA + acol,  Al + arow * H + acol);
        const bf16* Wh = W_hi + (size_t)kk * ldw + gcolB;
        const bf16* Wl = W_lo + (size_t)kk * ldw + gcolB;
        bf16* Bh = st + 2 * A_PLANE;
        bf16* Bl = Bh + B_PLANE;
        cp16(Bh + brow0 * SB + bcol0,        Wh + brow0 * ldw);
        cp16(Bh + (brow0 + 16) * SB + bcol0, Wh + (brow0 + 16) * ldw);
        cp16(Bl + brow0 * SB + bcol0,        Wl + brow0 * ldw);
        cp16(Bl + (brow0 + 16) * SB + bcol0, Wl + (brow0 + 16) * ldw);
        cp_commit();
    };

    issue(0);
    if (NIT > 1) issue(1);

    const uint32_t base = (uint32_t)__cvta_generic_to_shared(sm);

    for (int it = 0; it < NIT; ++it) {
        cp_wait<NSTAGE - 2>();
        __syncthreads();
        if (it + NSTAGE - 1 < NIT) issue(it + NSTAGE - 1);

        const int slot = it % NSTAGE;
        const uint32_t st  = base + (uint32_t)(slot * STAGE_ELEMS * 2);
        const uint32_t aHi = st;
        const uint32_t aLo = st + A_PLANE * 2;
        const uint32_t bHi = st + 4 * A_PLANE;   // 2 planes * 2 bytes
        const uint32_t bLo = bHi + B_PLANE * 2;

#pragma unroll
        for (int ks = 0; ks < 2; ks++) {
            uint32_t ah[2][4], al[2][4];
#pragma unroll
            for (int mf = 0; mf < 2; mf++) {
                int row = warp_m * 32 + mf * 16 + (lane & 15);
                int col = ks * 16 + (lane >> 4) * 8;
                uint32_t off = (uint32_t)((row * SA + col) * 2);
                ldsm_x4(ah[mf][0], ah[mf][1], ah[mf][2], ah[mf][3], aHi + off);
                ldsm_x4(al[mf][0], al[mf][1], al[mf][2], al[mf][3], aLo + off);
            }
            uint32_t bh[4][2], bl[4][2];
#pragma unroll
            for (int nf = 0; nf < 4; nf++) {
                int row = ks * 16 + (lane & 15);
                int col = nf * 32 + warp_n * 8;
                uint32_t off = (uint32_t)((row * SB + col) * 2);
                ldsm_x2t(bh[nf][0], bh[nf][1], bHi + off);
                ldsm_x2t(bl[nf][0], bl[nf][1], bLo + off);
            }
#pragma unroll
            for (int mf = 0; mf < 2; mf++)
#pragma unroll
                for (int nf = 0; nf < 4; nf++) {
                    mma16816(acc[mf][nf], ah[mf], bh[nf]);
                    mma16816(acc[mf][nf], ah[mf], bl[nf]);
                    mma16816(acc[mf][nf], al[mf], bh[nf]);
                }
        }
    }
    __syncthreads();
}

// ---------------- setup kernels ----------------
__global__ void prep_weights(const float* __restrict__ W_H2h,
                             const float* __restrict__ Wk,
                             const float* __restrict__ Wr) {
    int idx = blockIdx.x * blockDim.x + threadIdx.x;
    if (idx < H2 * H) {
        split_store(W_H2h[idx], &g_W2h[0][idx], &g_W2h[1][idx]);
    }
    if (idx < H * H4) {
        split_store(Wk[idx], &g_Wk[0][idx], &g_Wk[1][idx]);
        split_store(Wr[idx], &g_Wr[0][idx], &g_Wr[1][idx]);
    }
}

__global__ void init_state(const float* __restrict__ src, const float* __restrict__ tgt) {
    int idx = blockIdx.x * blockDim.x + threadIdx.x;
    const int n = S_LEN * BB * H;
    if (idx >= n) return;
    float s = src[idx], t = tgt[idx];
    ((float*)g_fSx)[idx] = s;
    ((float*)g_fTx)[idx] = t;
    ((float*)g_fSm)[idx] = 0.0f;
    ((float*)g_fTm)[idx] = 0.0f;
    split_store(s, &((bf16*)g_bSx[0])[idx], &((bf16*)g_bSx[1])[idx]);
    split_store(t, &((bf16*)g_bTx[0])[idx], &((bf16*)g_bTx[1])[idx]);
    bf16 z = __float2bfloat16(0.0f);
    ((bf16*)g_bSh[0])[idx] = z; ((bf16*)g_bSh[1])[idx] = z;
    ((bf16*)g_bTh[0])[idx] = z; ((bf16*)g_bTh[1])[idx] = z;
}

// ---------------- phase A ----------------
__global__ __launch_bounds__(256) void phaseA(int d, const float* __restrict__ b_H2h) {
    extern __shared__ __align__(16) bf16 sm[];

    const int i0 = (d - 31 > 0) ? d - 31 : 0;
    const int i = i0 + blockIdx.y;
    const int j = d - i;
    const int t = blockIdx.x;

    const int tid = threadIdx.x;
    const int lane = tid & 31;
    const int warp = tid >> 5;
    const int warp_m = warp >> 2;
    const int warp_n = warp & 3;
    const int r0 = warp_m * 32 + (lane >> 2);
    const int c0 = warp_n * 8 + (lane & 3) * 2;

    float acc[2][4][4];
#pragma unroll
    for (int a = 0; a < 2; a++)
#pragma unroll
        for (int b = 0; b < 4; b++)
#pragma unroll
            for (int c = 0; c < 4; c++) acc[a][b][c] = 0.0f;

    if (t < 4) {
        gemm_core<H2, true, false>(sm,
            g_bSh[0][i], g_bSh[1][i], g_bTh[0][j], g_bTh[1][j],
            g_W2h[0], g_W2h[1], H, t, acc);
#pragma unroll
        for (int mf = 0; mf < 2; mf++)
#pragma unroll
            for (int nf = 0; nf < 4; nf++)
#pragma unroll
                for (int rr = 0; rr < 2; rr++)
#pragma unroll
                    for (int cc = 0; cc < 2; cc++) {
                        int m = r0 + mf * 16 + rr * 8;
                        int n = t * 128 + nf * 32 + c0 + cc;
                        float v = acc[mf][nf][rr * 2 + cc] + b_H2h[n];
                        split_store(v, &g_bHm[0][i][m * H + n], &g_bHm[1][i][m * H + n]);
                    }
    } else if (t < 20) {
        int nblk = t - 4;
        gemm_core<H, false, false>(sm,
            g_bSx[0][i], g_bSx[1][i], nullptr, nullptr,
            g_Wk[0], g_Wk[1], H4, nblk, acc);
#pragma unroll
        for (int mf = 0; mf < 2; mf++)
#pragma unroll
            for (int nf = 0; nf < 4; nf++)
#pragma unroll
                for (int rr = 0; rr < 2; rr++)
#pragma unroll
                    for (int cc = 0; cc < 2; cc++) {
                        int m = r0 + mf * 16 + rr * 8;
                        int n = nblk * 128 + nf * 32 + c0 + cc;
                        g_fZS[i][m * H4 + n] = acc[mf][nf][rr * 2 + cc];
                    }
    } else {
        int nblk = t - 20;
        gemm_core<H, false, false>(sm,
            g_bTx[0][j], g_bTx[1][j], nullptr, nullptr,
            g_Wk[0], g_Wk[1], H4, nblk, acc);
#pragma unroll
        for (int mf = 0; mf < 2; mf++)
#pragma unroll
            for (int nf = 0; nf < 4; nf++)
#pragma unroll
                for (int rr = 0; rr < 2; rr++)
#pragma unroll
                    for (int cc = 0; cc < 2; cc++) {
                        int m = r0 + mf * 16 + rr * 8;
                        int n = nblk * 128 + nf * 32 + c0 + cc;
                        g_fZT[j][m * H4 + n] = acc[mf][nf][rr * 2 + cc];
                    }
    }
}

// ---------------- phase B: R GEMM + fused LSTM gates ----------------
__global__ __launch_bounds__(256) void phaseB(int d, const float* __restrict__ b_lstm) {
    extern __shared__ __align__(16) bf16 sm[];

    const int i0 = (d - 31 > 0) ? d - 31 : 0;
    const int i = i0 + blockIdx.y;
    const int j = d - i;
    const int nblk = blockIdx.x;

    const int tid = threadIdx.x;
    const int lane = tid & 31;
    const int warp = tid >> 5;
    const int warp_m = warp >> 2;
    const int warp_n = warp & 3;
    const int r0 = warp_m * 32 + (lane >> 2);
    const int c0 = warp_n * 8 + (lane & 3) * 2;

    float acc[2][4][4];
#pragma unroll
    for (int a = 0; a < 2; a++)
#pragma unroll
        for (int b = 0; b < 4; b++)
#pragma unroll
            for (int c = 0; c < 4; c++) acc[a][b][c] = 0.0f;

    gemm_core<H, false, true>(sm,
        g_bHm[0][i], g_bHm[1][i], nullptr, nullptr,
        g_Wr[0], g_Wr[1], H4, nblk, acc);

#pragma unroll
    for (int mf = 0; mf < 2; mf++)
#pragma unroll
        for (int rr = 0; rr < 2; rr++)
#pragma unroll
            for (int cc = 0; cc < 2; cc++) {
                const int m = r0 + mf * 16 + rr * 8;
                const int nn = nblk * 32 + c0 + cc;
                const int ridx = rr * 2 + cc;
                const float ri = acc[mf][0][ridx];
                const float rf = acc[mf][1][ridx];
                const float rg = acc[mf][2][ridx];
                const float ro = acc[mf][3][ridx];
                const float bi = b_lstm[nn];
                const float bfv = b_lstm[H + nn];
                const float bg = b_lstm[2 * H + nn];
                const float bo = b_lstm[3 * H + nn];
                {
                    float zi = ri + g_fZS[i][m * H4 + nn]         + bi;
                    float zf = rf + g_fZS[i][m * H4 + H + nn]     + bfv;
                    float zg = rg + g_fZS[i][m * H4 + 2 * H + nn] + bg;
                    float zo = ro + g_fZS[i][m * H4 + 3 * H + nn] + bo;
                    float c2 = sigf(zf) * g_fSm[i][m * H + nn] + sigf(zi) * tanh_fast(zg);
                    float h2 = sigf(zo) * tanh_fast(c2);
                    g_fSm[i][m * H + nn] = c2;
                    g_fSx[i][m * H + nn] = h2;
                    bf16 hi = __float2bfloat16(h2);
                    bf16 lo = __float2bfloat16(h2 - __bfloat162float(hi));
                    g_bSx[0][i][m * H + nn] = hi; g_bSx[1][i][m * H + nn] = lo;
                    g_bSh[0][i][m * H + nn] = hi; g_bSh[1][i][m * H + nn] = lo;
                }
                {
                    float zi = ri + g_fZT[j][m * H4 + nn]         + bi;
                    float zf = rf + g_fZT[j][m * H4 + H + nn]     + bfv;
                    float zg = rg + g_fZT[j][m * H4 + 2 * H + nn] + bg;
                    float zo = ro + g_fZT[j][m * H4 + 3 * H + nn] + bo;
                    float c2 = sigf(zf) * g_fTm[j][m * H + nn] + sigf(zi) * tanh_fast(zg);
                    float h2 = sigf(zo) * tanh_fast(c2);
                    g_fTm[j][m * H + nn] = c2;
                    g_fTx[j][m * H + nn] = h2;
                    bf16 hi = __float2bfloat16(h2);
                    bf16 lo = __float2bfloat16(h2 - __bfloat162float(hi));
                    g_bTx[0][j][m * H + nn] = hi; g_bTx[1][j][m * H + nn] = lo;
                    g_bTh[0][j][m * H + nn] = hi; g_bTh[1][j][m * H + nn] = lo;
                }
            }
}

__global__ void copy_out(float* __restrict__ out) {
    int idx = blockIdx.x * blockDim.x + threadIdx.x;
    const int n = S_LEN * BB * H;
    if (idx < n) {
        out[idx]     = ((float*)g_fSx)[idx];
        out[n + idx] = ((float*)g_fTx)[idx];
    }
}

extern "C" void kernel_launch(void* const* d_in, const int* in_sizes, int n_in,
                              void* d_out, int out_size) {
    const float* source = (const float*)d_in[0];
    const float* target = (const float*)d_in[1];
    const float* W_H2h  = (const float*)d_in[2];
    const float* b_H2h  = (const float*)d_in[3];
    const float* Wk     = (const float*)d_in[4];
    const float* Wr     = (const float*)d_in[5];
    const float* b_lstm = (const float*)d_in[6];
    float* out = (float*)d_out;

    static bool attr_set = false;
    if (!attr_set) {
        cudaFuncSetAttribute(phaseA, cudaFuncAttributeMaxDynamicSharedMemorySize, SMEM_BYTES);
        cudaFuncSetAttribute(phaseB, cudaFuncAttributeMaxDynamicSharedMemorySize, SMEM_BYTES);
        attr_set = true;
    }

    const int N = S_LEN * BB * H;
    prep_weights<<<(H * H4 + 255) / 256, 256>>>(W_H2h, Wk, Wr);
    init_state<<<(N + 255) / 256, 256>>>(source, target);

    for (int d = 0; d < 63; d++) {
        int lo = (d - 31 > 0) ? d - 31 : 0;
        int hi = (d < 31) ? d : 31;
        int nc = hi - lo + 1;
        phaseA<<<dim3(36, nc), 256, SMEM_BYTES>>>(d, b_H2h);
        phaseB<<<dim3(16, nc), 256, SMEM_BYTES>>>(d, b_lstm);
    }

    copy_out<<<(N + 255) / 256, 256>>>(out);
}

// round 6
// speedup vs baseline: 2.5846x; 1.1182x over previous
#include <cuda_runtime.h>
#include <cuda_bf16.h>
#include <stdint.h>
#include <math.h>

#define S_LEN 32
#define BB    64
#define H     512
#define H2    1024
#define H4    2048

typedef __nv_bfloat16 bf16;

// ---------------- persistent device state ----------------
__device__ bf16 g_W2h[2][H2 * H];
__device__ bf16 g_Wk [2][H * H4];
__device__ bf16 g_Wr [2][H * H4];
__device__ bf16 g_bSh[2][S_LEN][BB * H];
__device__ bf16 g_bTh[2][S_LEN][BB * H];
__device__ bf16 g_bSx[2][S_LEN][BB * H];
__device__ bf16 g_bTx[2][S_LEN][BB * H];
__device__ bf16 g_bHm[2][S_LEN][BB * H];
__device__ float g_fSm[S_LEN][BB * H];
__device__ float g_fTm[S_LEN][BB * H];
__device__ float g_fSx[S_LEN][BB * H];
__device__ float g_fTx[S_LEN][BB * H];
__device__ float g_fZS[S_LEN][BB * H4];
__device__ float g_fZT[S_LEN][BB * H4];

// ---------------- helpers ----------------
__device__ __forceinline__ float sigf(float x) { return 1.0f / (1.0f + __expf(-x)); }
__device__ __forceinline__ float tanh_fast(float x) {
    float e = __expf(2.0f * x);
    return 1.0f - 2.0f / (e + 1.0f);
}
__device__ __forceinline__ void split_store(float v, bf16* phi, bf16* plo) {
    bf16 hi = __float2bfloat16(v);
    bf16 lo = __float2bfloat16(v - __bfloat162float(hi));
    *phi = hi; *plo = lo;
}
__device__ __forceinline__ void cp16(void* smem, const void* g) {
    uint32_t s = (uint32_t)__cvta_generic_to_shared(smem);
    asm volatile("cp.async.cg.shared.global [%0], [%1], 16;\n" :: "r"(s), "l"(g));
}
__device__ __forceinline__ void cp_commit() { asm volatile("cp.async.commit_group;\n"); }
template<int N> __device__ __forceinline__ void cp_wait() {
    asm volatile("cp.async.wait_group %0;\n" :: "n"(N));
}
__device__ __forceinline__ void ldsm_x4(uint32_t& r0, uint32_t& r1, uint32_t& r2, uint32_t& r3, uint32_t addr) {
    asm volatile("ldmatrix.sync.aligned.m8n8.x4.shared.b16 {%0,%1,%2,%3},[%4];\n"
                 : "=r"(r0), "=r"(r1), "=r"(r2), "=r"(r3) : "r"(addr));
}
__device__ __forceinline__ void ldsm_x2t(uint32_t& r0, uint32_t& r1, uint32_t addr) {
    asm volatile("ldmatrix.sync.aligned.m8n8.x2.trans.shared.b16 {%0,%1},[%2];\n"
                 : "=r"(r0), "=r"(r1) : "r"(addr));
}
__device__ __forceinline__ void mma16816(float* d, const uint32_t* a, const uint32_t* b) {
    asm volatile("mma.sync.aligned.m16n8k16.row.col.f32.bf16.bf16.f32 "
                 "{%0,%1,%2,%3},{%4,%5,%6,%7},{%8,%9},{%0,%1,%2,%3};\n"
                 : "+f"(d[0]), "+f"(d[1]), "+f"(d[2]), "+f"(d[3])
                 : "r"(a[0]), "r"(a[1]), "r"(a[2]), "r"(a[3]), "r"(b[0]), "r"(b[1]));
}

// ---------------- split-K pass-fused GEMM core ----------------
// Block = 512 threads = 2 groups x 8 warps. Each group: BM=64, BN=128, BK=32
// over HALF of K, private 3-stage cp.async pipeline. Warp tile 32x32, 2m x 4n.
// Split-precision: hi*hi + hi*lo + lo*hi per K-tile.
#define SA 40
#define SB 136
#define A_PLANE (64 * SA)                       // 2560 elems
#define B_PLANE (32 * SB)                       // 4352 elems
#define STAGE_ELEMS (2 * A_PLANE + 2 * B_PLANE) // 13824 elems
#define NSTAGE 3
#define GROUP_ELEMS (NSTAGE * STAGE_ELEMS)      // 41472 elems
#define SMEM_BYTES (2 * GROUP_ELEMS * 2)        // 165888 bytes
#define SF_LD 132                               // fp32 reduce tile stride

template<int NIT, bool CONCAT, bool GSTRIDE>
__device__ __forceinline__ void gemm_core(
    bf16* smG, int kbase,
    const bf16* A_hi0, const bf16* A_lo0,
    const bf16* A_hi1, const bf16* A_lo1,
    const bf16* W_hi, const bf16* W_lo, int ldw,
    int nblk, float acc[2][4][4])
{
    const int tid = threadIdx.x;
    const int wg_tid = tid & 255;
    const int lane = tid & 31;
    const int wg_warp = (wg_tid >> 5);
    const int warp_m = wg_warp >> 2;
    const int warp_n = wg_warp & 3;

    const int arow = wg_tid >> 2;           // 0..63
    const int acol = (wg_tid & 3) * 8;      // 0,8,16,24
    const int brow0 = wg_tid >> 4;          // 0..15
    const int bcol0 = (wg_tid & 15) * 8;    // 0..120
    const int gcolB = GSTRIDE ? ((bcol0 >> 5) * H + nblk * 32 + (bcol0 & 31))
                              : (nblk * 128 + bcol0);

    auto issue = [&](int it) {
        int kk = kbase + it * 32;
        int slot = it % NSTAGE;
        bf16* st = smG + slot * STAGE_ELEMS;
        const bf16 *Ah, *Al;
        if (CONCAT && kk >= H) { Ah = A_hi1 + (kk - H); Al = A_lo1 + (kk - H); }
        else                   { Ah = A_hi0 + kk;       Al = A_lo0 + kk; }
        cp16(st + arow * SA + acol,            Ah + arow * H + acol);
        cp16(st + A_PLANE + arow * SA + acol,  Al + arow * H + acol);
        const bf16* Wh = W_hi + (size_t)kk * ldw + gcolB;
        const bf16* Wl = W_lo + (size_t)kk * ldw + gcolB;
        bf16* Bh = st + 2 * A_PLANE;
        bf16* Bl = Bh + B_PLANE;
        cp16(Bh + brow0 * SB + bcol0,        Wh + brow0 * ldw);
        cp16(Bh + (brow0 + 16) * SB + bcol0, Wh + (brow0 + 16) * ldw);
        cp16(Bl + brow0 * SB + bcol0,        Wl + brow0 * ldw);
        cp16(Bl + (brow0 + 16) * SB + bcol0, Wl + (brow0 + 16) * ldw);
        cp_commit();
    };

    issue(0);
    if (NIT > 1) issue(1);

    const uint32_t base = (uint32_t)__cvta_generic_to_shared(smG);

    for (int it = 0; it < NIT; ++it) {
        cp_wait<NSTAGE - 2>();
        __syncthreads();
        if (it + NSTAGE - 1 < NIT) issue(it + NSTAGE - 1);

        const int slot = it % NSTAGE;
        const uint32_t st  = base + (uint32_t)(slot * STAGE_ELEMS * 2);
        const uint32_t aHi = st;
        const uint32_t aLo = st + A_PLANE * 2;
        const uint32_t bHi = st + 4 * A_PLANE;
        const uint32_t bLo = bHi + B_PLANE * 2;

#pragma unroll
        for (int ks = 0; ks < 2; ks++) {
            uint32_t ah[2][4], al[2][4];
#pragma unroll
            for (int mf = 0; mf < 2; mf++) {
                int row = warp_m * 32 + mf * 16 + (lane & 15);
                int col = ks * 16 + (lane >> 4) * 8;
                uint32_t off = (uint32_t)((row * SA + col) * 2);
                ldsm_x4(ah[mf][0], ah[mf][1], ah[mf][2], ah[mf][3], aHi + off);
                ldsm_x4(al[mf][0], al[mf][1], al[mf][2], al[mf][3], aLo + off);
            }
            uint32_t bh[4][2], bl[4][2];
#pragma unroll
            for (int nf = 0; nf < 4; nf++) {
                int row = ks * 16 + (lane & 15);
                int col = nf * 32 + warp_n * 8;
                uint32_t off = (uint32_t)((row * SB + col) * 2);
                ldsm_x2t(bh[nf][0], bh[nf][1], bHi + off);
                ldsm_x2t(bl[nf][0], bl[nf][1], bLo + off);
            }
#pragma unroll
            for (int mf = 0; mf < 2; mf++)
#pragma unroll
                for (int nf = 0; nf < 4; nf++) {
                    mma16816(acc[mf][nf], ah[mf], bh[nf]);
                    mma16816(acc[mf][nf], ah[mf], bl[nf]);
                    mma16816(acc[mf][nf], al[mf], bh[nf]);
                }
        }
    }
    cp_wait<0>();
    __syncthreads();
}

// Reduce both groups' fragments into smem fp32 tile sf[64][SF_LD].
__device__ __forceinline__ void reduce_groups(bf16* sm, float acc[2][4][4]) {
    float* sf = (float*)sm;
    const int tid = threadIdx.x;
    const int group = tid >> 8;
    const int wg_tid = tid & 255;
    const int lane = tid & 31;
    const int wg_warp = wg_tid >> 5;
    const int warp_m = wg_warp >> 2;
    const int warp_n = wg_warp & 3;
    const int r0 = warp_m * 32 + (lane >> 2);
    const int c0 = warp_n * 8 + (lane & 3) * 2;

    if (group == 0) {
#pragma unroll
        for (int mf = 0; mf < 2; mf++)
#pragma unroll
            for (int nf = 0; nf < 4; nf++)
#pragma unroll
                for (int rr = 0; rr < 2; rr++)
#pragma unroll
                    for (int cc = 0; cc < 2; cc++) {
                        int m = r0 + mf * 16 + rr * 8;
                        int c = nf * 32 + c0 + cc;
                        sf[m * SF_LD + c] = acc[mf][nf][rr * 2 + cc];
                    }
    }
    __syncthreads();
    if (group == 1) {
#pragma unroll
        for (int mf = 0; mf < 2; mf++)
#pragma unroll
            for (int nf = 0; nf < 4; nf++)
#pragma unroll
                for (int rr = 0; rr < 2; rr++)
#pragma unroll
                    for (int cc = 0; cc < 2; cc++) {
                        int m = r0 + mf * 16 + rr * 8;
                        int c = nf * 32 + c0 + cc;
                        sf[m * SF_LD + c] += acc[mf][nf][rr * 2 + cc];
                    }
    }
    __syncthreads();
}

// ---------------- setup kernels ----------------
__global__ void prep_weights(const float* __restrict__ W_H2h,
                             const float* __restrict__ Wk,
                             const float* __restrict__ Wr) {
    int idx = blockIdx.x * blockDim.x + threadIdx.x;
    if (idx < H2 * H) {
        split_store(W_H2h[idx], &g_W2h[0][idx], &g_W2h[1][idx]);
    }
    if (idx < H * H4) {
        split_store(Wk[idx], &g_Wk[0][idx], &g_Wk[1][idx]);
        split_store(Wr[idx], &g_Wr[0][idx], &g_Wr[1][idx]);
    }
}

__global__ void init_state(const float* __restrict__ src, const float* __restrict__ tgt) {
    int idx = blockIdx.x * blockDim.x + threadIdx.x;
    const int n = S_LEN * BB * H;
    if (idx >= n) return;
    float s = src[idx], t = tgt[idx];
    ((float*)g_fSx)[idx] = s;
    ((float*)g_fTx)[idx] = t;
    ((float*)g_fSm)[idx] = 0.0f;
    ((float*)g_fTm)[idx] = 0.0f;
    split_store(s, &((bf16*)g_bSx[0])[idx], &((bf16*)g_bSx[1])[idx]);
    split_store(t, &((bf16*)g_bTx[0])[idx], &((bf16*)g_bTx[1])[idx]);
    bf16 z = __float2bfloat16(0.0f);
    ((bf16*)g_bSh[0])[idx] = z; ((bf16*)g_bSh[1])[idx] = z;
    ((bf16*)g_bTh[0])[idx] = z; ((bf16*)g_bTh[1])[idx] = z;
}

// ---------------- phase A ----------------
__global__ __launch_bounds__(512, 1) void phaseA(int d, const float* __restrict__ b_H2h) {
    extern __shared__ __align__(16) bf16 sm[];

    const int i0 = (d - 31 > 0) ? d - 31 : 0;
    const int i = i0 + blockIdx.y;
    const int j = d - i;
    const int t = blockIdx.x;

    const int tid = threadIdx.x;
    const int group = tid >> 8;
    bf16* smG = sm + group * GROUP_ELEMS;

    float acc[2][4][4];
#pragma unroll
    for (int a = 0; a < 2; a++)
#pragma unroll
        for (int b = 0; b < 4; b++)
#pragma unroll
            for (int c = 0; c < 4; c++) acc[a][b][c] = 0.0f;

    float* sf = (float*)sm;

    if (t < 4) {
        // hmid: K=1024, group g handles K range [g*512, g*512+512)
        gemm_core<16, true, false>(smG, group * 512,
            g_bSh[0][i], g_bSh[1][i], g_bTh[0][j], g_bTh[1][j],
            g_W2h[0], g_W2h[1], H, t, acc);
        reduce_groups(sm, acc);
        for (int idx = tid; idx < 64 * 128; idx += 512) {
            int m = idx >> 7;
            int c = idx & 127;
            int n = t * 128 + c;
            float v = sf[m * SF_LD + c] + b_H2h[n];
            split_store(v, &g_bHm[0][i][m * H + n], &g_bHm[1][i][m * H + n]);
        }
    } else if (t < 20) {
        int nblk = t - 4;
        gemm_core<8, false, false>(smG, group * 256,
            g_bSx[0][i], g_bSx[1][i], nullptr, nullptr,
            g_Wk[0], g_Wk[1], H4, nblk, acc);
        reduce_groups(sm, acc);
        for (int idx = tid; idx < 64 * 128; idx += 512) {
            int m = idx >> 7;
            int c = idx & 127;
            g_fZS[i][m * H4 + nblk * 128 + c] = sf[m * SF_LD + c];
        }
    } else {
        int nblk = t - 20;
        gemm_core<8, false, false>(smG, group * 256,
            g_bTx[0][j], g_bTx[1][j], nullptr, nullptr,
            g_Wk[0], g_Wk[1], H4, nblk, acc);
        reduce_groups(sm, acc);
        for (int idx = tid; idx < 64 * 128; idx += 512) {
            int m = idx >> 7;
            int c = idx & 127;
            g_fZT[j][m * H4 + nblk * 128 + c] = sf[m * SF_LD + c];
        }
    }
}

// ---------------- phase B: R GEMM + fused LSTM gates ----------------
__global__ __launch_bounds__(512, 1) void phaseB(int d, const float* __restrict__ b_lstm) {
    extern __shared__ __align__(16) bf16 sm[];

    const int i0 = (d - 31 > 0) ? d - 31 : 0;
    const int i = i0 + blockIdx.y;
    const int j = d - i;
    const int nblk = blockIdx.x;

    const int tid = threadIdx.x;
    const int group = tid >> 8;
    bf16* smG = sm + group * GROUP_ELEMS;

    float acc[2][4][4];
#pragma unroll
    for (int a = 0; a < 2; a++)
#pragma unroll
        for (int b = 0; b < 4; b++)
#pragma unroll
            for (int c = 0; c < 4; c++) acc[a][b][c] = 0.0f;

    gemm_core<8, false, true>(smG, group * 256,
        g_bHm[0][i], g_bHm[1][i], nullptr, nullptr,
        g_Wr[0], g_Wr[1], H4, nblk, acc);
    reduce_groups(sm, acc);

    float* sf = (float*)sm;
    // 64 rows x 32 output columns; sf col layout = gate*32 + nl
    for (int idx = tid; idx < 64 * 32; idx += 512) {
        const int m = idx >> 5;
        const int nl = idx & 31;
        const int nn = nblk * 32 + nl;
        const float ri = sf[m * SF_LD + 0 * 32 + nl];
        const float rf = sf[m * SF_LD + 1 * 32 + nl];
        const float rg = sf[m * SF_LD + 2 * 32 + nl];
        const float ro = sf[m * SF_LD + 3 * 32 + nl];
        const float bi = b_lstm[nn];
        const float bfv = b_lstm[H + nn];
        const float bg = b_lstm[2 * H + nn];
        const float bo = b_lstm[3 * H + nn];
        {
            float zi = ri + g_fZS[i][m * H4 + nn]         + bi;
            float zf = rf + g_fZS[i][m * H4 + H + nn]     + bfv;
            float zg = rg + g_fZS[i][m * H4 + 2 * H + nn] + bg;
            float zo = ro + g_fZS[i][m * H4 + 3 * H + nn] + bo;
            float c2 = sigf(zf) * g_fSm[i][m * H + nn] + sigf(zi) * tanh_fast(zg);
            float h2 = sigf(zo) * tanh_fast(c2);
            g_fSm[i][m * H + nn] = c2;
            g_fSx[i][m * H + nn] = h2;
            bf16 hi = __float2bfloat16(h2);
            bf16 lo = __float2bfloat16(h2 - __bfloat162float(hi));
            g_bSx[0][i][m * H + nn] = hi; g_bSx[1][i][m * H + nn] = lo;
            g_bSh[0][i][m * H + nn] = hi; g_bSh[1][i][m * H + nn] = lo;
        }
        {
            float zi = ri + g_fZT[j][m * H4 + nn]         + bi;
            float zf = rf + g_fZT[j][m * H4 + H + nn]     + bfv;
            float zg = rg + g_fZT[j][m * H4 + 2 * H + nn] + bg;
            float zo = ro + g_fZT[j][m * H4 + 3 * H + nn] + bo;
            float c2 = sigf(zf) * g_fTm[j][m * H + nn] + sigf(zi) * tanh_fast(zg);
            float h2 = sigf(zo) * tanh_fast(c2);
            g_fTm[j][m * H + nn] = c2;
            g_fTx[j][m * H + nn] = h2;
            bf16 hi = __float2bfloat16(h2);
            bf16 lo = __float2bfloat16(h2 - __bfloat162float(hi));
            g_bTx[0][j][m * H + nn] = hi; g_bTx[1][j][m * H + nn] = lo;
            g_bTh[0][j][m * H + nn] = hi; g_bTh[1][j][m * H + nn] = lo;
        }
    }
}

__global__ void copy_out(float* __restrict__ out) {
    int idx = blockIdx.x * blockDim.x + threadIdx.x;
    const int n = S_LEN * BB * H;
    if (idx < n) {
        out[idx]     = ((float*)g_fSx)[idx];
        out[n + idx] = ((float*)g_fTx)[idx];
    }
}

extern "C" void kernel_launch(void* const* d_in, const int* in_sizes, int n_in,
                              void* d_out, int out_size) {
    const float* source = (const float*)d_in[0];
    const float* target = (const float*)d_in[1];
    const float* W_H2h  = (const float*)d_in[2];
    const float* b_H2h  = (const float*)d_in[3];
    const float* Wk     = (const float*)d_in[4];
    const float* Wr     = (const float*)d_in[5];
    const float* b_lstm = (const float*)d_in[6];
    float* out = (float*)d_out;

    cudaFuncSetAttribute(phaseA, cudaFuncAttributeMaxDynamicSharedMemorySize, SMEM_BYTES);
    cudaFuncSetAttribute(phaseB, cudaFuncAttributeMaxDynamicSharedMemorySize, SMEM_BYTES);

    const int N = S_LEN * BB * H;
    prep_weights<<<(H * H4 + 255) / 256, 256>>>(W_H2h, Wk, Wr);
    init_state<<<(N + 255) / 256, 256>>>(source, target);

    for (int d = 0; d < 63; d++) {
        int lo = (d - 31 > 0) ? d - 31 : 0;
        int hi = (d < 31) ? d : 31;
        int nc = hi - lo + 1;
        phaseA<<<dim3(36, nc), 512, SMEM_BYTES>>>(d, b_H2h);
        phaseB<<<dim3(16, nc), 512, SMEM_BYTES>>>(d, b_lstm);
    }

    copy_out<<<(N + 255) / 256, 256>>>(out);
}

// round 7
// speedup vs baseline: 2.6821x; 1.0377x over previous
#include <cuda_runtime.h>
#include <cuda_bf16.h>
#include <stdint.h>
#include <math.h>

#define S_LEN 32
#define BB    64
#define H     512
#define H2    1024
#define H4    2048

typedef __nv_bfloat16 bf16;

// ---------------- persistent device state ----------------
__device__ bf16 g_W2h[2][H2 * H];
__device__ bf16 g_Wk [2][H * H4];
__device__ bf16 g_Wr [2][H * H4];
__device__ bf16 g_bSh[2][S_LEN][BB * H];
__device__ bf16 g_bTh[2][S_LEN][BB * H];
__device__ bf16 g_bSx[2][S_LEN][BB * H];
__device__ bf16 g_bTx[2][S_LEN][BB * H];
__device__ bf16 g_bHm[2][S_LEN][BB * H];
__device__ float g_fSm[S_LEN][BB * H];
__device__ float g_fTm[S_LEN][BB * H];
__device__ float g_fSx[S_LEN][BB * H];
__device__ float g_fTx[S_LEN][BB * H];
__device__ float g_fZS[S_LEN][BB * H4];
__device__ float g_fZT[S_LEN][BB * H4];

// grid barrier state
__device__ unsigned g_bar_count = 0;
__device__ volatile unsigned g_bar_gen = 0;

// ---------------- helpers ----------------
__device__ __forceinline__ float sigf(float x) { return 1.0f / (1.0f + __expf(-x)); }
__device__ __forceinline__ float tanh_fast(float x) {
    float e = __expf(2.0f * x);
    return 1.0f - 2.0f / (e + 1.0f);
}
__device__ __forceinline__ void split_store(float v, bf16* phi, bf16* plo) {
    bf16 hi = __float2bfloat16(v);
    bf16 lo = __float2bfloat16(v - __bfloat162float(hi));
    *phi = hi; *plo = lo;
}
__device__ __forceinline__ void cp16(void* smem, const void* g) {
    uint32_t s = (uint32_t)__cvta_generic_to_shared(smem);
    asm volatile("cp.async.cg.shared.global [%0], [%1], 16;\n" :: "r"(s), "l"(g));
}
__device__ __forceinline__ void cp_commit() { asm volatile("cp.async.commit_group;\n"); }
template<int N> __device__ __forceinline__ void cp_wait() {
    asm volatile("cp.async.wait_group %0;\n" :: "n"(N));
}
__device__ __forceinline__ void ldsm_x4(uint32_t& r0, uint32_t& r1, uint32_t& r2, uint32_t& r3, uint32_t addr) {
    asm volatile("ldmatrix.sync.aligned.m8n8.x4.shared.b16 {%0,%1,%2,%3},[%4];\n"
                 : "=r"(r0), "=r"(r1), "=r"(r2), "=r"(r3) : "r"(addr));
}
__device__ __forceinline__ void ldsm_x2t(uint32_t& r0, uint32_t& r1, uint32_t addr) {
    asm volatile("ldmatrix.sync.aligned.m8n8.x2.trans.shared.b16 {%0,%1},[%2];\n"
                 : "=r"(r0), "=r"(r1) : "r"(addr));
}
__device__ __forceinline__ void mma16816(float* d, const uint32_t* a, const uint32_t* b) {
    asm volatile("mma.sync.aligned.m16n8k16.row.col.f32.bf16.bf16.f32 "
                 "{%0,%1,%2,%3},{%4,%5,%6,%7},{%8,%9},{%0,%1,%2,%3};\n"
                 : "+f"(d[0]), "+f"(d[1]), "+f"(d[2]), "+f"(d[3])
                 : "r"(a[0]), "r"(a[1]), "r"(a[2]), "r"(a[3]), "r"(b[0]), "r"(b[1]));
}

__device__ __forceinline__ void grid_barrier() {
    __syncthreads();
    if (threadIdx.x == 0) {
        __threadfence();
        unsigned gen = g_bar_gen;
        if (atomicInc(&g_bar_count, gridDim.x - 1) == gridDim.x - 1) {
            g_bar_gen = gen + 1;
        } else {
            while (g_bar_gen == gen) { __nanosleep(32); }
        }
    }
    __syncthreads();
}

// ---------------- split-K pass-fused GEMM core ----------------
// Block = 512 threads = 2 groups x 8 warps. Each group: BM=64, BN=128, BK=32
// over HALF of K, private 3-stage cp.async pipeline. Warp tile 32x32, 2m x 4n.
// Split-precision: hi*hi + hi*lo + lo*hi per K-tile.
#define SA 40
#define SB 136
#define A_PLANE (64 * SA)
#define B_PLANE (32 * SB)
#define STAGE_ELEMS (2 * A_PLANE + 2 * B_PLANE)
#define NSTAGE 3
#define GROUP_ELEMS (NSTAGE * STAGE_ELEMS)
#define SMEM_BYTES (2 * GROUP_ELEMS * 2)   // 165888 bytes
#define SF_LD 132

template<int NIT, bool CONCAT, bool GSTRIDE>
__device__ __forceinline__ void gemm_core(
    bf16* smG, int kbase,
    const bf16* A_hi0, const bf16* A_lo0,
    const bf16* A_hi1, const bf16* A_lo1,
    const bf16* W_hi, const bf16* W_lo, int ldw,
    int nblk, float acc[2][4][4])
{
    const int tid = threadIdx.x;
    const int wg_tid = tid & 255;
    const int lane = tid & 31;
    const int wg_warp = (wg_tid >> 5);
    const int warp_m = wg_warp >> 2;
    const int warp_n = wg_warp & 3;

    const int arow = wg_tid >> 2;
    const int acol = (wg_tid & 3) * 8;
    const int brow0 = wg_tid >> 4;
    const int bcol0 = (wg_tid & 15) * 8;
    const int gcolB = GSTRIDE ? ((bcol0 >> 5) * H + nblk * 32 + (bcol0 & 31))
                              : (nblk * 128 + bcol0);

    auto issue = [&](int it) {
        int kk = kbase + it * 32;
        int slot = it % NSTAGE;
        bf16* st = smG + slot * STAGE_ELEMS;
        const bf16 *Ah, *Al;
        if (CONCAT && kk >= H) { Ah = A_hi1 + (kk - H); Al = A_lo1 + (kk - H); }
        else                   { Ah = A_hi0 + kk;       Al = A_lo0 + kk; }
        cp16(st + arow * SA + acol,            Ah + arow * H + acol);
        cp16(st + A_PLANE + arow * SA + acol,  Al + arow * H + acol);
        const bf16* Wh = W_hi + (size_t)kk * ldw + gcolB;
        const bf16* Wl = W_lo + (size_t)kk * ldw + gcolB;
        bf16* Bh = st + 2 * A_PLANE;
        bf16* Bl = Bh + B_PLANE;
        cp16(Bh + brow0 * SB + bcol0,        Wh + brow0 * ldw);
        cp16(Bh + (brow0 + 16) * SB + bcol0, Wh + (brow0 + 16) * ldw);
        cp16(Bl + brow0 * SB + bcol0,        Wl + brow0 * ldw);
        cp16(Bl + (brow0 + 16) * SB + bcol0, Wl + (brow0 + 16) * ldw);
        cp_commit();
    };

    issue(0);
    if (NIT > 1) issue(1);

    const uint32_t base = (uint32_t)__cvta_generic_to_shared(smG);

    for (int it = 0; it < NIT; ++it) {
        cp_wait<NSTAGE - 2>();
        __syncthreads();
        if (it + NSTAGE - 1 < NIT) issue(it + NSTAGE - 1);

        const int slot = it % NSTAGE;
        const uint32_t st  = base + (uint32_t)(slot * STAGE_ELEMS * 2);
        const uint32_t aHi = st;
        const uint32_t aLo = st + A_PLANE * 2;
        const uint32_t bHi = st + 4 * A_PLANE;
        const uint32_t bLo = bHi + B_PLANE * 2;

#pragma unroll
        for (int ks = 0; ks < 2; ks++) {
            uint32_t ah[2][4], al[2][4];
#pragma unroll
            for (int mf = 0; mf < 2; mf++) {
                int row = warp_m * 32 + mf * 16 + (lane & 15);
                int col = ks * 16 + (lane >> 4) * 8;
                uint32_t off = (uint32_t)((row * SA + col) * 2);
                ldsm_x4(ah[mf][0], ah[mf][1], ah[mf][2], ah[mf][3], aHi + off);
                ldsm_x4(al[mf][0], al[mf][1], al[mf][2], al[mf][3], aLo + off);
            }
            uint32_t bh[4][2], bl[4][2];
#pragma unroll
            for (int nf = 0; nf < 4; nf++) {
                int row = ks * 16 + (lane & 15);
                int col = nf * 32 + warp_n * 8;
                uint32_t off = (uint32_t)((row * SB + col) * 2);
                ldsm_x2t(bh[nf][0], bh[nf][1], bHi + off);
                ldsm_x2t(bl[nf][0], bl[nf][1], bLo + off);
            }
#pragma unroll
            for (int mf = 0; mf < 2; mf++)
#pragma unroll
                for (int nf = 0; nf < 4; nf++) {
                    mma16816(acc[mf][nf], ah[mf], bh[nf]);
                    mma16816(acc[mf][nf], ah[mf], bl[nf]);
                    mma16816(acc[mf][nf], al[mf], bh[nf]);
                }
        }
    }
    cp_wait<0>();
    __syncthreads();
}

// Reduce both groups' fragments into smem fp32 tile sf[64][SF_LD].
__device__ __forceinline__ void reduce_groups(bf16* sm, float acc[2][4][4]) {
    float* sf = (float*)sm;
    const int tid = threadIdx.x;
    const int group = tid >> 8;
    const int wg_tid = tid & 255;
    const int lane = tid & 31;
    const int wg_warp = wg_tid >> 5;
    const int warp_m = wg_warp >> 2;
    const int warp_n = wg_warp & 3;
    const int r0 = warp_m * 32 + (lane >> 2);
    const int c0 = warp_n * 8 + (lane & 3) * 2;

    if (group == 0) {
#pragma unroll
        for (int mf = 0; mf < 2; mf++)
#pragma unroll
            for (int nf = 0; nf < 4; nf++)
#pragma unroll
                for (int rr = 0; rr < 2; rr++)
#pragma unroll
                    for (int cc = 0; cc < 2; cc++) {
                        int m = r0 + mf * 16 + rr * 8;
                        int c = nf * 32 + c0 + cc;
                        sf[m * SF_LD + c] = acc[mf][nf][rr * 2 + cc];
                    }
    }
    __syncthreads();
    if (group == 1) {
#pragma unroll
        for (int mf = 0; mf < 2; mf++)
#pragma unroll
            for (int nf = 0; nf < 4; nf++)
#pragma unroll
                for (int rr = 0; rr < 2; rr++)
#pragma unroll
                    for (int cc = 0; cc < 2; cc++) {
                        int m = r0 + mf * 16 + rr * 8;
                        int c = nf * 32 + c0 + cc;
                        sf[m * SF_LD + c] += acc[mf][nf][rr * 2 + cc];
                    }
    }
    __syncthreads();
}

// ---------------- setup kernels ----------------
__global__ void prep_weights(const float* __restrict__ W_H2h,
                             const float* __restrict__ Wk,
                             const float* __restrict__ Wr) {
    int idx = blockIdx.x * blockDim.x + threadIdx.x;
    if (idx < H2 * H) {
        split_store(W_H2h[idx], &g_W2h[0][idx], &g_W2h[1][idx]);
    }
    if (idx < H * H4) {
        split_store(Wk[idx], &g_Wk[0][idx], &g_Wk[1][idx]);
        split_store(Wr[idx], &g_Wr[0][idx], &g_Wr[1][idx]);
    }
}

__global__ void init_state(const float* __restrict__ src, const float* __restrict__ tgt) {
    int idx = blockIdx.x * blockDim.x + threadIdx.x;
    const int n = S_LEN * BB * H;
    if (idx >= n) return;
    float s = src[idx], t = tgt[idx];
    ((float*)g_fSx)[idx] = s;
    ((float*)g_fTx)[idx] = t;
    ((float*)g_fSm)[idx] = 0.0f;
    ((float*)g_fTm)[idx] = 0.0f;
    split_store(s, &((bf16*)g_bSx[0])[idx], &((bf16*)g_bSx[1])[idx]);
    split_store(t, &((bf16*)g_bTx[0])[idx], &((bf16*)g_bTx[1])[idx]);
    bf16 z = __float2bfloat16(0.0f);
    ((bf16*)g_bSh[0])[idx] = z; ((bf16*)g_bSh[1])[idx] = z;
    ((bf16*)g_bTh[0])[idx] = z; ((bf16*)g_bTh[1])[idx] = z;
}

// ---------------- persistent grid kernel: all 63 waves ----------------
__global__ __launch_bounds__(512, 1) void grid_kernel(const float* __restrict__ b_H2h,
                                                      const float* __restrict__ b_lstm,
                                                      float* __restrict__ out) {
    extern __shared__ __align__(16) bf16 sm[];
    const int tid = threadIdx.x;
    const int group = tid >> 8;
    bf16* smG = sm + group * GROUP_ELEMS;
    float* sf = (float*)sm;

    for (int d = 0; d < 63; d++) {
        const int lo = (d - 31 > 0) ? d - 31 : 0;
        const int hi = (d < 31) ? d : 31;
        const int nc = hi - lo + 1;

        // ---------------- phase A ----------------
        const int nwA = 36 * nc;
        for (int w = blockIdx.x; w < nwA; w += gridDim.x) {
            const int c = w / 36;
            const int t = w - c * 36;
            const int i = lo + c;
            const int j = d - i;

            float acc[2][4][4];
#pragma unroll
            for (int a = 0; a < 2; a++)
#pragma unroll
                for (int b = 0; b < 4; b++)
#pragma unroll
                    for (int cc = 0; cc < 4; cc++) acc[a][b][cc] = 0.0f;

            if (t < 4) {
                gemm_core<16, true, false>(smG, group * 512,
                    g_bSh[0][i], g_bSh[1][i], g_bTh[0][j], g_bTh[1][j],
                    g_W2h[0], g_W2h[1], H, t, acc);
                reduce_groups(sm, acc);
                for (int idx = tid; idx < 64 * 128; idx += 512) {
                    int m = idx >> 7;
                    int cl = idx & 127;
                    int n = t * 128 + cl;
                    float v = sf[m * SF_LD + cl] + b_H2h[n];
                    split_store(v, &g_bHm[0][i][m * H + n], &g_bHm[1][i][m * H + n]);
                }
            } else if (t < 20) {
                int nblk = t - 4;
                gemm_core<8, false, false>(smG, group * 256,
                    g_bSx[0][i], g_bSx[1][i], nullptr, nullptr,
                    g_Wk[0], g_Wk[1], H4, nblk, acc);
                reduce_groups(sm, acc);
                for (int idx = tid; idx < 64 * 128; idx += 512) {
                    int m = idx >> 7;
                    int cl = idx & 127;
                    g_fZS[i][m * H4 + nblk * 128 + cl] = sf[m * SF_LD + cl];
                }
            } else {
                int nblk = t - 20;
                gemm_core<8, false, false>(smG, group * 256,
                    g_bTx[0][j], g_bTx[1][j], nullptr, nullptr,
                    g_Wk[0], g_Wk[1], H4, nblk, acc);
                reduce_groups(sm, acc);
                for (int idx = tid; idx < 64 * 128; idx += 512) {
                    int m = idx >> 7;
                    int cl = idx & 127;
                    g_fZT[j][m * H4 + nblk * 128 + cl] = sf[m * SF_LD + cl];
                }
            }
            __syncthreads();
        }
        grid_barrier();

        // ---------------- phase B ----------------
        const int nwB = 16 * nc;
        for (int w = blockIdx.x; w < nwB; w += gridDim.x) {
            const int c = w >> 4;
            const int nblk = w & 15;
            const int i = lo + c;
            const int j = d - i;

            float acc[2][4][4];
#pragma unroll
            for (int a = 0; a < 2; a++)
#pragma unroll
                for (int b = 0; b < 4; b++)
#pragma unroll
                    for (int cc = 0; cc < 4; cc++) acc[a][b][cc] = 0.0f;

            gemm_core<8, false, true>(smG, group * 256,
                g_bHm[0][i], g_bHm[1][i], nullptr, nullptr,
                g_Wr[0], g_Wr[1], H4, nblk, acc);
            reduce_groups(sm, acc);

            for (int idx = tid; idx < 64 * 32; idx += 512) {
                const int m = idx >> 5;
                const int nl = idx & 31;
                const int nn = nblk * 32 + nl;
                const float ri = sf[m * SF_LD + 0 * 32 + nl];
                const float rf = sf[m * SF_LD + 1 * 32 + nl];
                const float rg = sf[m * SF_LD + 2 * 32 + nl];
                const float ro = sf[m * SF_LD + 3 * 32 + nl];
                const float bi = b_lstm[nn];
                const float bfv = b_lstm[H + nn];
                const float bg = b_lstm[2 * H + nn];
                const float bo = b_lstm[3 * H + nn];
                {
                    float zi = ri + __ldcg(&g_fZS[i][m * H4 + nn])         + bi;
                    float zf = rf + __ldcg(&g_fZS[i][m * H4 + H + nn])     + bfv;
                    float zg = rg + __ldcg(&g_fZS[i][m * H4 + 2 * H + nn]) + bg;
                    float zo = ro + __ldcg(&g_fZS[i][m * H4 + 3 * H + nn]) + bo;
                    float c2 = sigf(zf) * __ldcg(&g_fSm[i][m * H + nn]) + sigf(zi) * tanh_fast(zg);
                    float h2 = sigf(zo) * tanh_fast(c2);
                    g_fSm[i][m * H + nn] = c2;
                    g_fSx[i][m * H + nn] = h2;
                    bf16 hib = __float2bfloat16(h2);
                    bf16 lob = __float2bfloat16(h2 - __bfloat162float(hib));
                    g_bSx[0][i][m * H + nn] = hib; g_bSx[1][i][m * H + nn] = lob;
                    g_bSh[0][i][m * H + nn] = hib; g_bSh[1][i][m * H + nn] = lob;
                }
                {
                    float zi = ri + __ldcg(&g_fZT[j][m * H4 + nn])         + bi;
                    float zf = rf + __ldcg(&g_fZT[j][m * H4 + H + nn])     + bfv;
                    float zg = rg + __ldcg(&g_fZT[j][m * H4 + 2 * H + nn]) + bg;
                    float zo = ro + __ldcg(&g_fZT[j][m * H4 + 3 * H + nn]) + bo;
                    float c2 = sigf(zf) * __ldcg(&g_fTm[j][m * H + nn]) + sigf(zi) * tanh_fast(zg);
                    float h2 = sigf(zo) * tanh_fast(c2);
                    g_fTm[j][m * H + nn] = c2;
                    g_fTx[j][m * H + nn] = h2;
                    bf16 hib = __float2bfloat16(h2);
                    bf16 lob = __float2bfloat16(h2 - __bfloat162float(hib));
                    g_bTx[0][j][m * H + nn] = hib; g_bTx[1][j][m * H + nn] = lob;
                    g_bTh[0][j][m * H + nn] = hib; g_bTh[1][j][m * H + nn] = lob;
                }
            }
            __syncthreads();
        }
        grid_barrier();
    }

    // ---------------- output ----------------
    const int n = S_LEN * BB * H;
    for (int idx = blockIdx.x * blockDim.x + tid; idx < n; idx += gridDim.x * blockDim.x) {
        out[idx]     = __ldcg(&((float*)g_fSx)[idx]);
        out[n + idx] = __ldcg(&((float*)g_fTx)[idx]);
    }
}

extern "C" void kernel_launch(void* const* d_in, const int* in_sizes, int n_in,
                              void* d_out, int out_size) {
    const float* source = (const float*)d_in[0];
    const float* target = (const float*)d_in[1];
    const float* W_H2h  = (const float*)d_in[2];
    const float* b_H2h  = (const float*)d_in[3];
    const float* Wk     = (const float*)d_in[4];
    const float* Wr     = (const float*)d_in[5];
    const float* b_lstm = (const float*)d_in[6];
    float* out = (float*)d_out;

    static int nsm = 0;
    if (nsm == 0) {
        cudaDeviceGetAttribute(&nsm, cudaDevAttrMultiProcessorCount, 0);
        cudaFuncSetAttribute(grid_kernel, cudaFuncAttributeMaxDynamicSharedMemorySize, SMEM_BYTES);
    }

    const int N = S_LEN * BB * H;
    prep_weights<<<(H * H4 + 255) / 256, 256>>>(W_H2h, Wk, Wr);
    init_state<<<(N + 255) / 256, 256>>>(source, target);
    grid_kernel<<<nsm, 512, SMEM_BYTES>>>(b_H2h, b_lstm, out);
}